// round 2
// baseline (speedup 1.0000x reference)
#include <cuda_runtime.h>

#define D_IN 33600
#define H1   1000
#define NCH1 448      // layer-1 row chunks
#define RPC1 75       // rows per chunk (448*75 = 33600)

#define NS   307      // needed layer-2 columns (x2[15k+1])
#define KC2  40       // layer-2 k chunks
#define RPC2 25       // rows per chunk (40*25 = 1000)

// ---------------- scratch (__device__ globals; no allocations) ----------------
__device__ float g_part1[NCH1 * H1];         // layer-1 partial sums
__device__ float g_h1[H1];                   // relu(layer-1)
__device__ float g_part2[KC2 * 320];         // layer-2 partials for the 307 scalars
__device__ float g_sp1[20 * 16 * 5121];      // seg1 k-split partials
__device__ float g_sp2[4 * 32 * 257];
__device__ float g_sp3[2 * 256 * 321];
__device__ float g_sp4[4 * 3 * 1542];

// ---------------- layer 1: partial GEMV, 448 blocks x 256 thr ----------------
__global__ void k_l1_partial(const float* __restrict__ x, const float* __restrict__ W) {
    __shared__ float xs[RPC1];
    int bx = blockIdx.x, tid = threadIdx.x;
    int i0 = bx * RPC1;
    if (tid < RPC1) xs[tid] = x[i0 + tid];
    __syncthreads();
    if (tid < 250) {
        const float4* W4 = (const float4*)W;   // 1000 floats/row = 250 float4, 16B aligned
        float4 a = make_float4(0.f, 0.f, 0.f, 0.f);
        #pragma unroll 5
        for (int r = 0; r < RPC1; ++r) {
            float4 w = W4[(size_t)(i0 + r) * 250 + tid];
            float xv = xs[r];
            a.x = fmaf(xv, w.x, a.x);
            a.y = fmaf(xv, w.y, a.y);
            a.z = fmaf(xv, w.z, a.z);
            a.w = fmaf(xv, w.w, a.w);
        }
        ((float4*)g_part1)[bx * 250 + tid] = a;
    }
}

// ---------------- layer 1 reduce: 32 blocks x 256 thr (32 j x 8 groups) ------
__global__ void k_l1_reduce(const float* __restrict__ bd1) {
    __shared__ float red[256];
    int tid = threadIdx.x;
    int lane = tid & 31, g = tid >> 5;
    int j = blockIdx.x * 32 + lane;
    float v = 0.f;
    if (j < H1) {
        int c0 = g * 56;                      // 448 / 8 = 56
        #pragma unroll 8
        for (int c = 0; c < 56; ++c)
            v += g_part1[(c0 + c) * H1 + j];
    }
    red[tid] = v;
    __syncthreads();
    if (g == 0 && j < H1) {
        float s = 0.f;
        #pragma unroll
        for (int gg = 0; gg < 8; ++gg) s += red[gg * 32 + lane];
        g_h1[j] = fmaxf(bd1[j] + s, 0.f);
    }
}

// ---------------- layer 2: only the 307 needed columns, k-split --------------
__global__ void k_l2_partial(const float* __restrict__ Wd2) {
    __shared__ float hs[RPC2];
    int tid = threadIdx.x, bx = blockIdx.x;
    int i0 = bx * RPC2;
    if (tid < RPC2) hs[tid] = g_h1[i0 + tid];
    __syncthreads();
    if (tid < NS) {
        float acc = 0.f;
        const float* base = Wd2 + (size_t)i0 * 4605 + 15 * tid + 1;
        #pragma unroll 5
        for (int r = 0; r < RPC2; ++r)
            acc = fmaf(hs[r], base[(size_t)r * 4605], acc);
        g_part2[bx * 320 + tid] = acc;
    }
}

// ---------------- segment body: j-tile in shared, k-split partial ------------
// Block covers JB scalars x (256*CPT) output cols for one k-chunk.
template<int JB, int CPT>
__device__ __forceinline__ void seg_body(
    const float* __restrict__ bd2,
    const float* __restrict__ Wa, const float* __restrict__ ba,
    const float* __restrict__ Wb, float* __restrict__ sp,
    int N, int H, int O, int sbase,
    int jb, int ct, int kt, int k0, int kcnt)
{
    __shared__ float s_sh[JB];
    __shared__ float h_sh[JB * 64];
    int tid = threadIdx.x;

    // scalar inputs: s[k] = relu(bd2[15k+1] + sum of layer-2 partials)
    if (tid < JB) {
        int ks = sbase + jb * JB + tid;
        float v = bd2[15 * ks + 1];
        #pragma unroll 8
        for (int c = 0; c < KC2; ++c) v += g_part2[c * 320 + ks];
        s_sh[tid] = fmaxf(v, 0.f);
    }
    __syncthreads();

    // hidden activations for this k-chunk
    for (int idx = tid; idx < JB * kcnt; idx += 256) {
        int j = idx / kcnt, r = idx - j * kcnt;
        int k = k0 + r;
        h_sh[j * kcnt + r] = fmaxf(fmaf(s_sh[j], Wa[k], ba[k]), 0.f);
    }
    __syncthreads();

    int nb = ct * (256 * CPT) + tid;
    float acc[JB * CPT];
    #pragma unroll
    for (int i = 0; i < JB * CPT; ++i) acc[i] = 0.f;

    for (int r = 0; r < kcnt; ++r) {
        const float* wrow = Wb + (size_t)(k0 + r) * O;
        float w[CPT];
        #pragma unroll
        for (int c = 0; c < CPT; ++c) {
            int n = nb + c * 256;
            w[c] = (n < O) ? wrow[n] : 0.f;
        }
        #pragma unroll
        for (int j = 0; j < JB; ++j) {
            float hv = h_sh[j * kcnt + r];   // warp-broadcast LDS
            #pragma unroll
            for (int c = 0; c < CPT; ++c)
                acc[j * CPT + c] = fmaf(hv, w[c], acc[j * CPT + c]);
        }
    }

    int jg0 = jb * JB;
    #pragma unroll
    for (int j = 0; j < JB; ++j) {
        #pragma unroll
        for (int c = 0; c < CPT; ++c) {
            int n = nb + c * 256;
            if (n < O)
                sp[((size_t)kt * N + (jg0 + j)) * O + n] = acc[j * CPT + c];
        }
    }
}

// seg1: 16x500x5121  JB=8 CPT=4: 6 ct x 2 jb x 20 kt = 240 blocks
// seg2: 32x100x257   JB=8 CPT=1: 2 ct x 4 jb x 4 kt  =  32 blocks
// seg3: 256x100x321  JB=8 CPT=1: 2 ct x 32 jb x 2 kt = 128 blocks
// seg4: 3x100x1542   JB=3 CPT=2: 4 ct x 1 jb x 4 kt  =  16 blocks
__global__ void k_segments(
    const float* __restrict__ bd2,
    const float* __restrict__ W1a, const float* __restrict__ b1a, const float* __restrict__ W1b,
    const float* __restrict__ W2a, const float* __restrict__ b2a, const float* __restrict__ W2b,
    const float* __restrict__ W3a, const float* __restrict__ b3a, const float* __restrict__ W3b,
    const float* __restrict__ W4a, const float* __restrict__ b4a, const float* __restrict__ W4b)
{
    int b = blockIdx.x;
    if (b < 240) {
        int kt = b / 12, rem = b % 12, jb = rem / 6, ct = rem % 6;
        seg_body<8, 4>(bd2, W1a, b1a, W1b, g_sp1, 16, 500, 5121, 0, jb, ct, kt, kt * 25, 25);
    } else if (b < 272) {
        int l = b - 240; int kt = l / 8, jb = (l % 8) / 2, ct = l % 2;
        seg_body<8, 1>(bd2, W2a, b2a, W2b, g_sp2, 32, 100, 257, 16, jb, ct, kt, kt * 25, 25);
    } else if (b < 400) {
        int l = b - 272; int kt = l / 64, jb = (l % 64) / 2, ct = l % 2;
        seg_body<8, 1>(bd2, W3a, b3a, W3b, g_sp3, 256, 100, 321, 48, jb, ct, kt, kt * 50, 50);
    } else {
        int l = b - 400; int kt = l / 4, ct = l % 4;
        seg_body<3, 2>(bd2, W4a, b4a, W4b, g_sp4, 3, 100, 1542, 304, 0, ct, kt, kt * 25, 25);
    }
}

// ---------------- combine: fold k-split partials + bias + relu ---------------
__global__ void k_combine(float* __restrict__ out,
    const float* __restrict__ b1b, const float* __restrict__ b2b,
    const float* __restrict__ b3b, const float* __restrict__ b4b)
{
    int idx = blockIdx.x * 256 + threadIdx.x;
    if (idx >= 176962) return;
    float v;
    if (idx < 81936) {                         // seg1: 16 x 5121
        int j = idx / 5121, n = idx - j * 5121;
        v = b1b[n];
        #pragma unroll
        for (int kt = 0; kt < 20; ++kt) v += g_sp1[((size_t)kt * 16 + j) * 5121 + n];
    } else if (idx < 90160) {                  // seg2: 32 x 257
        int l = idx - 81936; int j = l / 257, n = l - j * 257;
        v = b2b[n];
        #pragma unroll
        for (int kt = 0; kt < 4; ++kt) v += g_sp2[(kt * 32 + j) * 257 + n];
    } else if (idx < 172336) {                 // seg3: 256 x 321
        int l = idx - 90160; int j = l / 321, n = l - j * 321;
        v = b3b[n];
        #pragma unroll
        for (int kt = 0; kt < 2; ++kt) v += g_sp3[(kt * 256 + j) * 321 + n];
    } else {                                   // seg4: 3 x 1542
        int l = idx - 172336; int j = l / 1542, n = l - j * 1542;
        v = b4b[n];
        #pragma unroll
        for (int kt = 0; kt < 4; ++kt) v += g_sp4[(kt * 3 + j) * 1542 + n];
    }
    out[idx] = fmaxf(v, 0.f);
}

extern "C" void kernel_launch(void* const* d_in, const int* in_sizes, int n_in,
                              void* d_out, int out_size) {
    const float* x   = (const float*)d_in[0];
    const float* Wd1 = (const float*)d_in[1];
    const float* bd1 = (const float*)d_in[2];
    const float* Wd2 = (const float*)d_in[3];
    const float* bd2 = (const float*)d_in[4];
    const float* W1a = (const float*)d_in[5];
    const float* b1a = (const float*)d_in[6];
    const float* W1b = (const float*)d_in[7];
    const float* b1b = (const float*)d_in[8];
    const float* W2a = (const float*)d_in[9];
    const float* b2a = (const float*)d_in[10];
    const float* W2b = (const float*)d_in[11];
    const float* b2b = (const float*)d_in[12];
    const float* W3a = (const float*)d_in[13];
    const float* b3a = (const float*)d_in[14];
    const float* W3b = (const float*)d_in[15];
    const float* b3b = (const float*)d_in[16];
    const float* W4a = (const float*)d_in[17];
    const float* b4a = (const float*)d_in[18];
    const float* W4b = (const float*)d_in[19];
    const float* b4b = (const float*)d_in[20];

    k_l1_partial<<<NCH1, 256>>>(x, Wd1);
    k_l1_reduce<<<32, 256>>>(bd1);
    k_l2_partial<<<KC2, 320>>>(Wd2);
    k_segments<<<416, 256>>>(bd2, W1a, b1a, W1b, W2a, b2a, W2b,
                             W3a, b3a, W3b, W4a, b4a, W4b);
    k_combine<<<(176962 + 255) / 256, 256>>>((float*)d_out, b1b, b2b, b3b, b4b);
}

// round 3
// speedup vs baseline: 1.0854x; 1.0854x over previous
#include <cuda_runtime.h>

#define D_IN 33600
#define H1   1000
#define NCH1 448      // layer-1 row chunks
#define RPC1 75       // rows per chunk (448*75 = 33600)

#define NS   307      // needed layer-2 columns (x2[15k+1])
#define KC2  40       // layer-2 k chunks
#define RPC2 25       // rows per chunk (40*25 = 1000)

#define KT1  10       // seg1 k-split chunks (500/10 = 50 each)

// ---------------- scratch (__device__ globals; no allocations) ----------------
__device__ float g_part1[NCH1 * H1];         // layer-1 partial sums [chunk][j]
__device__ float g_part2[KC2 * 320];         // layer-2 partials for the 307 scalars
__device__ float g_sp1[KT1 * 16 * 5121];     // seg1 k-split partials

// ---------------- layer 1: partial GEMV, 448 blocks x 256 thr ----------------
__global__ void k_l1_partial(const float* __restrict__ x, const float* __restrict__ W) {
    __shared__ float xs[RPC1];
    int bx = blockIdx.x, tid = threadIdx.x;
    int i0 = bx * RPC1;
    if (tid < RPC1) xs[tid] = x[i0 + tid];
    __syncthreads();
    if (tid < 250) {
        const float4* W4 = (const float4*)W;   // 1000 floats/row = 250 float4
        float4 a = make_float4(0.f, 0.f, 0.f, 0.f);
        #pragma unroll 15
        for (int r = 0; r < RPC1; ++r) {
            float4 w = W4[(size_t)(i0 + r) * 250 + tid];
            float xv = xs[r];
            a.x = fmaf(xv, w.x, a.x);
            a.y = fmaf(xv, w.y, a.y);
            a.z = fmaf(xv, w.z, a.z);
            a.w = fmaf(xv, w.w, a.w);
        }
        ((float4*)g_part1)[bx * 250 + tid] = a;
    }
}

// -------- mid: fold layer-1 partials -> h1 (shared), then layer-2 partials ---
// 40 blocks x 320 threads; block bx owns h1 rows [bx*25, bx*25+25)
__global__ void k_mid(const float* __restrict__ bd1, const float* __restrict__ Wd2) {
    __shared__ float red[200];
    __shared__ float hs[RPC2];
    int tid = threadIdx.x, bx = blockIdx.x;
    int i0 = bx * RPC2;

    if (tid < 200) {                           // 25 rows x 8 chunk-groups
        int jj = tid % 25, g = tid / 25;
        float v = 0.f;
        int c0 = g * 56;                       // 448/8
        #pragma unroll 8
        for (int c = 0; c < 56; ++c)
            v += g_part1[(c0 + c) * H1 + i0 + jj];
        red[tid] = v;
    }
    __syncthreads();
    if (tid < RPC2) {
        float s = bd1[i0 + tid];
        #pragma unroll
        for (int g = 0; g < 8; ++g) s += red[g * 25 + tid];
        hs[tid] = fmaxf(s, 0.f);
    }
    __syncthreads();
    if (tid < NS) {
        float acc = 0.f;
        const float* base = Wd2 + (size_t)i0 * 4605 + 15 * tid + 1;
        #pragma unroll 5
        for (int r = 0; r < RPC2; ++r)
            acc = fmaf(hs[r], base[(size_t)r * 4605], acc);
        g_part2[bx * 320 + tid] = acc;
    }
}

// ---------------- segment body -----------------------------------------------
// Block covers JB scalars x (256*CPT) columns over k range [k0, k0+kcnt).
// If bb != nullptr: writes final (bias+relu). Else: writes raw partial.
template<int JB, int CPT>
__device__ __forceinline__ void seg_body(
    const float* __restrict__ bd2,
    const float* __restrict__ Wa, const float* __restrict__ ba,
    const float* __restrict__ Wb, const float* __restrict__ bb,
    float* __restrict__ dst,
    int O, int sbase, int jg0, int k0, int kcnt, int ct)
{
    __shared__ float s_sh[16];
    __shared__ float h_sh[800];                // [r][JB], max 50*16 / 100*4
    int tid = threadIdx.x;

    if (tid < JB) {
        int ks = sbase + jg0 + tid;
        float v = bd2[15 * ks + 1];
        #pragma unroll
        for (int c = 0; c < KC2; ++c) v += g_part2[c * 320 + ks];
        s_sh[tid] = fmaxf(v, 0.f);
    }
    __syncthreads();
    for (int idx = tid; idx < JB * kcnt; idx += 256) {
        int r = idx / JB, j = idx - r * JB;
        int k = k0 + r;
        h_sh[r * JB + j] = fmaxf(fmaf(s_sh[j], Wa[k], ba[k]), 0.f);
    }
    __syncthreads();

    int nb = ct * (256 * CPT) + tid;
    float acc[JB * CPT];
    #pragma unroll
    for (int i = 0; i < JB * CPT; ++i) acc[i] = 0.f;

    for (int r = 0; r < kcnt; ++r) {
        const float* wrow = Wb + (size_t)(k0 + r) * O;
        float w[CPT];
        #pragma unroll
        for (int c = 0; c < CPT; ++c) {
            int n = nb + c * 256;
            w[c] = (n < O) ? wrow[n] : 0.f;
        }
        const float* hr = &h_sh[r * JB];
        #pragma unroll
        for (int j = 0; j < JB; ++j) {
            float hv = hr[j];                  // broadcast LDS (float4-packable)
            #pragma unroll
            for (int c = 0; c < CPT; ++c)
                acc[j * CPT + c] = fmaf(hv, w[c], acc[j * CPT + c]);
        }
    }

    #pragma unroll
    for (int j = 0; j < JB; ++j) {
        #pragma unroll
        for (int c = 0; c < CPT; ++c) {
            int n = nb + c * 256;
            if (n < O) {
                float v = acc[j * CPT + c];
                if (bb) v = fmaxf(v + bb[n], 0.f);
                dst[(size_t)(jg0 + j) * O + n] = v;
            }
        }
    }
}

// seg1: 16x500x5121  JB=16 CPT=1: 10 kt x 21 ct = 210 blocks (partial)
// seg3: 256x100x321  JB=4  CPT=2: 64 jb                      (direct)
// seg2: 32x100x257   JB=4  CPT=2: 8 jb                       (direct)
// seg4: 3x100x1542   JB=3  CPT=1: 7 ct                       (direct)
__global__ void k_segments(
    float* __restrict__ out,
    const float* __restrict__ bd2,
    const float* __restrict__ W1a, const float* __restrict__ b1a, const float* __restrict__ W1b,
    const float* __restrict__ W2a, const float* __restrict__ b2a, const float* __restrict__ W2b, const float* __restrict__ b2b,
    const float* __restrict__ W3a, const float* __restrict__ b3a, const float* __restrict__ W3b, const float* __restrict__ b3b,
    const float* __restrict__ W4a, const float* __restrict__ b4a, const float* __restrict__ W4b, const float* __restrict__ b4b)
{
    int b = blockIdx.x;
    if (b < 210) {
        int kt = b / 21, ct = b % 21;
        seg_body<16, 1>(bd2, W1a, b1a, W1b, nullptr,
                        g_sp1 + (size_t)kt * 16 * 5121,
                        5121, 0, 0, kt * 50, 50, ct);
    } else if (b < 274) {
        int jb = b - 210;
        seg_body<4, 2>(bd2, W3a, b3a, W3b, b3b, out + 90160,
                       321, 48, jb * 4, 0, 100, 0);
    } else if (b < 282) {
        int jb = b - 274;
        seg_body<4, 2>(bd2, W2a, b2a, W2b, b2b, out + 81936,
                       257, 16, jb * 4, 0, 100, 0);
    } else {
        int ct = b - 282;
        seg_body<3, 1>(bd2, W4a, b4a, W4b, b4b, out + 172336,
                       1542, 304, 0, 0, 100, ct);
    }
}

// ---------------- combine: seg1 only (fold 10 k-partials + bias + relu) ------
__global__ void k_combine(float* __restrict__ out, const float* __restrict__ b1b) {
    int idx = blockIdx.x * 256 + threadIdx.x;
    if (idx >= 81936) return;                  // 16 x 5121
    int j = idx / 5121, n = idx - j * 5121;
    float v = b1b[n];
    #pragma unroll
    for (int kt = 0; kt < KT1; ++kt)
        v += g_sp1[((size_t)kt * 16 + j) * 5121 + n];
    out[idx] = fmaxf(v, 0.f);
}

extern "C" void kernel_launch(void* const* d_in, const int* in_sizes, int n_in,
                              void* d_out, int out_size) {
    const float* x   = (const float*)d_in[0];
    const float* Wd1 = (const float*)d_in[1];
    const float* bd1 = (const float*)d_in[2];
    const float* Wd2 = (const float*)d_in[3];
    const float* bd2 = (const float*)d_in[4];
    const float* W1a = (const float*)d_in[5];
    const float* b1a = (const float*)d_in[6];
    const float* W1b = (const float*)d_in[7];
    const float* b1b = (const float*)d_in[8];
    const float* W2a = (const float*)d_in[9];
    const float* b2a = (const float*)d_in[10];
    const float* W2b = (const float*)d_in[11];
    const float* b2b = (const float*)d_in[12];
    const float* W3a = (const float*)d_in[13];
    const float* b3a = (const float*)d_in[14];
    const float* W3b = (const float*)d_in[15];
    const float* b3b = (const float*)d_in[16];
    const float* W4a = (const float*)d_in[17];
    const float* b4a = (const float*)d_in[18];
    const float* W4b = (const float*)d_in[19];
    const float* b4b = (const float*)d_in[20];
    float* out = (float*)d_out;

    k_l1_partial<<<NCH1, 256>>>(x, Wd1);
    k_mid<<<KC2, 320>>>(bd1, Wd2);
    k_segments<<<289, 256>>>(out, bd2,
                             W1a, b1a, W1b,
                             W2a, b2a, W2b, b2b,
                             W3a, b3a, W3b, b3b,
                             W4a, b4a, W4b, b4b);
    k_combine<<<(81936 + 255) / 256, 256>>>(out, b1b);
}

// round 4
// speedup vs baseline: 1.4765x; 1.3603x over previous
#include <cuda_runtime.h>

#define H1   1000
#define NCH1 672      // layer-1 row chunks
#define RPC1 50       // rows per chunk (672*50 = 33600)

#define NS   307      // needed layer-2 columns (x2[15k+1])
#define KC2  40       // layer-2 k chunks
#define RPC2 25       // rows per chunk (40*25 = 1000)

// ---------------- scratch (__device__ globals; no allocations) ----------------
__device__ float g_part1[NCH1 * H1];         // layer-1 partial sums [chunk][j]
__device__ float g_part2[KC2 * 320];         // layer-2 partials for the 307 scalars

// ---------------- layer 1: partial GEMV, 672 blocks x 256 thr ----------------
__global__ void k_l1_partial(const float* __restrict__ x, const float* __restrict__ W) {
    __shared__ float xs[RPC1];
    int bx = blockIdx.x, tid = threadIdx.x;
    int i0 = bx * RPC1;
    if (tid < RPC1) xs[tid] = x[i0 + tid];
    __syncthreads();
    if (tid < 250) {
        const float4* W4 = (const float4*)W;   // 1000 floats/row = 250 float4
        float4 a = make_float4(0.f, 0.f, 0.f, 0.f);
        #pragma unroll 10
        for (int r = 0; r < RPC1; ++r) {
            float4 w = __ldcs(&W4[(size_t)(i0 + r) * 250 + tid]);
            float xv = xs[r];
            a.x = fmaf(xv, w.x, a.x);
            a.y = fmaf(xv, w.y, a.y);
            a.z = fmaf(xv, w.z, a.z);
            a.w = fmaf(xv, w.w, a.w);
        }
        ((float4*)g_part1)[bx * 250 + tid] = a;
    }
}

// -------- mid: fold layer-1 partials -> h1 (shared), then layer-2 partials ---
// 40 blocks x 320 threads; block bx owns h1 rows [bx*25, bx*25+25)
__global__ void k_mid(const float* __restrict__ bd1, const float* __restrict__ Wd2) {
    __shared__ float red[200];
    __shared__ float hs[RPC2];
    int tid = threadIdx.x, bx = blockIdx.x;
    int i0 = bx * RPC2;

    if (tid < 200) {                           // 25 rows x 8 chunk-groups
        int jj = tid % 25, g = tid / 25;
        float v = 0.f;
        int c0 = g * 84;                       // 672/8
        #pragma unroll 12
        for (int c = 0; c < 84; ++c)
            v += g_part1[(c0 + c) * H1 + i0 + jj];
        red[tid] = v;
    }
    __syncthreads();
    if (tid < RPC2) {
        float s = bd1[i0 + tid];
        #pragma unroll
        for (int g = 0; g < 8; ++g) s += red[g * 25 + tid];
        hs[tid] = fmaxf(s, 0.f);
    }
    __syncthreads();
    if (tid < NS) {
        float acc = 0.f;
        const float* base = Wd2 + (size_t)i0 * 4605 + 15 * tid + 1;
        #pragma unroll 5
        for (int r = 0; r < RPC2; ++r)
            acc = fmaf(hs[r], base[(size_t)r * 4605], acc);
        g_part2[bx * 320 + tid] = acc;
    }
}

// ---------------- shared helpers ---------------------------------------------
__device__ __forceinline__ void fold_scalars(float* s_sh, const float* __restrict__ bd2,
                                             int sbase, int JB) {
    int tid = threadIdx.x;
    if (tid < JB) {
        int ks = sbase + tid;
        float v = bd2[15 * ks + 1];
        #pragma unroll
        for (int c = 0; c < KC2; ++c) v += g_part2[c * 320 + ks];
        s_sh[tid] = fmaxf(v, 0.f);
    }
}

// ---- seg1: 16 x 500 x 5121. warp-split-k, smem reduce, direct final write ---
// smem partition: s[0:16], h[16:16+8064] (504 rows x 16), red[8080:8080+4096]
__device__ __forceinline__ void seg1_body(
    float* smem, float* __restrict__ out, const float* __restrict__ bd2,
    const float* __restrict__ Wa, const float* __restrict__ ba,
    const float* __restrict__ Wb, const float* __restrict__ bb, int blk)
{
    const int O = 5121;
    float* s_sh = smem;
    float* h_sh = smem + 16;
    float* red  = smem + 8080;
    int tid = threadIdx.x;

    fold_scalars(s_sh, bd2, 0, 16);
    __syncthreads();

    // hidden: h[k][j] for k in [0,504), zero-padded beyond 500
    #pragma unroll
    for (int k = tid; k < 504; k += 256) {
        float av = 0.f, bv = 0.f;
        if (k < 500) { av = Wa[k]; bv = ba[k]; }
        float* hk = &h_sh[k * 16];
        #pragma unroll
        for (int j = 0; j < 16; ++j) {
            float v = (k < 500) ? fmaxf(fmaf(s_sh[j], av, bv), 0.f) : 0.f;
            hk[j] = v;
        }
    }
    __syncthreads();

    int w = tid >> 5, lane = tid & 31;
    int n = blk * 32 + lane;
    bool nok = (n < O);
    int k0 = w * 63;

    float acc[16];
    #pragma unroll
    for (int j = 0; j < 16; ++j) acc[j] = 0.f;

    #pragma unroll 9
    for (int r = 0; r < 63; ++r) {
        int k = k0 + r;
        float wv = (nok && k < 500) ? Wb[(size_t)k * O + n] : 0.f;
        const float* hr = &h_sh[k * 16];
        #pragma unroll
        for (int j = 0; j < 16; ++j)
            acc[j] = fmaf(hr[j], wv, acc[j]);
    }

    // reduce 8 warps in shared: red[w][j][lane]
    #pragma unroll
    for (int j = 0; j < 16; ++j)
        red[w * 512 + j * 32 + lane] = acc[j];
    __syncthreads();

    #pragma unroll
    for (int p = tid; p < 512; p += 256) {
        int j = p >> 5, ln = p & 31;
        int nn = blk * 32 + ln;
        if (nn < O) {
            float v = bb[nn];
            #pragma unroll
            for (int ww = 0; ww < 8; ++ww) v += red[ww * 512 + p];
            out[(size_t)j * O + nn] = fmaxf(v, 0.f);
        }
    }
}

// ---- direct segment: JB scalars x (256*CPT) cols, full K=100, final write ---
template<int JB, int CPT>
__device__ __forceinline__ void seg_direct(
    float* smem, float* __restrict__ out, const float* __restrict__ bd2,
    const float* __restrict__ Wa, const float* __restrict__ ba,
    const float* __restrict__ Wb, const float* __restrict__ bb,
    int O, int sbase, int jg0, int ct)
{
    float* s_sh = smem;
    float* h_sh = smem + 16;                   // [k][JB], 100*JB <= 400
    int tid = threadIdx.x;

    fold_scalars(s_sh, bd2, sbase + jg0, JB);
    __syncthreads();

    if (tid < 100) {
        float av = Wa[tid], bv = ba[tid];
        float* hk = &h_sh[tid * JB];
        #pragma unroll
        for (int j = 0; j < JB; ++j)
            hk[j] = fmaxf(fmaf(s_sh[j], av, bv), 0.f);
    }
    __syncthreads();

    int nb = ct * (256 * CPT) + tid;
    float acc[JB * CPT];
    #pragma unroll
    for (int i = 0; i < JB * CPT; ++i) acc[i] = 0.f;

    #pragma unroll 10
    for (int r = 0; r < 100; ++r) {
        const float* wrow = Wb + (size_t)r * O;
        float w[CPT];
        #pragma unroll
        for (int c = 0; c < CPT; ++c) {
            int n = nb + c * 256;
            w[c] = (n < O) ? wrow[n] : 0.f;
        }
        const float* hr = &h_sh[r * JB];
        #pragma unroll
        for (int j = 0; j < JB; ++j) {
            float hv = hr[j];
            #pragma unroll
            for (int c = 0; c < CPT; ++c)
                acc[j * CPT + c] = fmaf(hv, w[c], acc[j * CPT + c]);
        }
    }

    #pragma unroll
    for (int j = 0; j < JB; ++j) {
        #pragma unroll
        for (int c = 0; c < CPT; ++c) {
            int n = nb + c * 256;
            if (n < O)
                out[(size_t)(jg0 + j) * O + n] = fmaxf(acc[j * CPT + c] + bb[n], 0.f);
        }
    }
}

// seg1: 161 blocks (5121/32)   | seg3: 64 blocks (256 j / 4)
// seg2: 8 blocks (32 j / 4)    | seg4: 7 blocks (1542 cols / 256)
__global__ void __launch_bounds__(256) k_segments(
    float* __restrict__ out,
    const float* __restrict__ bd2,
    const float* __restrict__ W1a, const float* __restrict__ b1a, const float* __restrict__ W1b, const float* __restrict__ b1b,
    const float* __restrict__ W2a, const float* __restrict__ b2a, const float* __restrict__ W2b, const float* __restrict__ b2b,
    const float* __restrict__ W3a, const float* __restrict__ b3a, const float* __restrict__ W3b, const float* __restrict__ b3b,
    const float* __restrict__ W4a, const float* __restrict__ b4a, const float* __restrict__ W4b, const float* __restrict__ b4b)
{
    __shared__ float smem[12192];
    int b = blockIdx.x;
    if (b < 161) {
        seg1_body(smem, out, bd2, W1a, b1a, W1b, b1b, b);
    } else if (b < 225) {
        int jb = b - 161;
        seg_direct<4, 2>(smem, out + 90160, bd2, W3a, b3a, W3b, b3b, 321, 48, jb * 4, 0);
    } else if (b < 233) {
        int jb = b - 225;
        seg_direct<4, 2>(smem, out + 81936, bd2, W2a, b2a, W2b, b2b, 257, 16, jb * 4, 0);
    } else {
        int ct = b - 233;
        seg_direct<3, 1>(smem, out + 172336, bd2, W4a, b4a, W4b, b4b, 1542, 304, 0, ct);
    }
}

extern "C" void kernel_launch(void* const* d_in, const int* in_sizes, int n_in,
                              void* d_out, int out_size) {
    const float* x   = (const float*)d_in[0];
    const float* Wd1 = (const float*)d_in[1];
    const float* bd1 = (const float*)d_in[2];
    const float* Wd2 = (const float*)d_in[3];
    const float* bd2 = (const float*)d_in[4];
    const float* W1a = (const float*)d_in[5];
    const float* b1a = (const float*)d_in[6];
    const float* W1b = (const float*)d_in[7];
    const float* b1b = (const float*)d_in[8];
    const float* W2a = (const float*)d_in[9];
    const float* b2a = (const float*)d_in[10];
    const float* W2b = (const float*)d_in[11];
    const float* b2b = (const float*)d_in[12];
    const float* W3a = (const float*)d_in[13];
    const float* b3a = (const float*)d_in[14];
    const float* W3b = (const float*)d_in[15];
    const float* b3b = (const float*)d_in[16];
    const float* W4a = (const float*)d_in[17];
    const float* b4a = (const float*)d_in[18];
    const float* W4b = (const float*)d_in[19];
    const float* b4b = (const float*)d_in[20];
    float* out = (float*)d_out;

    k_l1_partial<<<NCH1, 256>>>(x, Wd1);
    k_mid<<<KC2, 320>>>(bd1, Wd2);
    k_segments<<<240, 256>>>(out, bd2,
                             W1a, b1a, W1b, b1b,
                             W2a, b2a, W2b, b2b,
                             W3a, b3a, W3b, b3b,
                             W4a, b4a, W4b, b4b);
}

// round 6
// speedup vs baseline: 1.5399x; 1.0429x over previous
#include <cuda_runtime.h>

#define H1   1000
#define NCH1 1344     // layer-1 row chunks
#define RPC1 25       // rows per chunk (1344*25 = 33600)

#define NS   307      // needed layer-2 columns (x2[15k+1])
#define KC2  40       // layer-2 k chunks
#define RPC2 25       // rows per chunk (40*25 = 1000)

// ---------------- scratch (__device__ globals; no allocations) ----------------
__device__ float g_part1[NCH1 * H1];         // layer-1 partial sums [chunk][j]
__device__ float g_part2[KC2 * 320];         // layer-2 partials for the 307 scalars

// ---------------- layer 1: partial GEMV, 1344 blocks x 256 thr ---------------
__global__ void __launch_bounds__(256) k_l1_partial(const float* __restrict__ x,
                                                    const float* __restrict__ W) {
    __shared__ float xs[RPC1];
    int bx = blockIdx.x, tid = threadIdx.x;
    int i0 = bx * RPC1;
    if (tid < RPC1) xs[tid] = x[i0 + tid];
    __syncthreads();
    if (tid < 250) {
        const float4* W4 = (const float4*)W;   // 1000 floats/row = 250 float4
        float4 a = make_float4(0.f, 0.f, 0.f, 0.f);
        #pragma unroll
        for (int r = 0; r < RPC1; ++r) {
            float4 w = __ldcs(&W4[(size_t)(i0 + r) * 250 + tid]);
            float xv = xs[r];
            a.x = fmaf(xv, w.x, a.x);
            a.y = fmaf(xv, w.y, a.y);
            a.z = fmaf(xv, w.z, a.z);
            a.w = fmaf(xv, w.w, a.w);
        }
        ((float4*)g_part1)[bx * 250 + tid] = a;
    }
}

// -------- mid: fold layer-1 partials -> h1 (shared), then layer-2 partials ---
// 40 blocks x 512 threads; block bx owns h1 rows [bx*25, bx*25+25)
__global__ void __launch_bounds__(512) k_mid(const float* __restrict__ bd1,
                                             const float* __restrict__ Wd2) {
    __shared__ float red[400];
    __shared__ float hs[RPC2];
    int tid = threadIdx.x, bx = blockIdx.x;
    int i0 = bx * RPC2;

    if (tid < 400) {                           // 25 rows x 16 chunk-groups
        int jj = tid % 25, g = tid / 25;
        float v = 0.f;
        int c0 = g * 84;                       // 1344/16
        #pragma unroll 12
        for (int c = 0; c < 84; ++c)
            v += g_part1[(c0 + c) * H1 + i0 + jj];
        red[tid] = v;
    }
    __syncthreads();
    if (tid < RPC2) {
        float s = bd1[i0 + tid];
        #pragma unroll
        for (int g = 0; g < 16; ++g) s += red[g * 25 + tid];
        hs[tid] = fmaxf(s, 0.f);
    }
    __syncthreads();
    if (tid < NS) {
        float acc = 0.f;
        const float* base = Wd2 + (size_t)i0 * 4605 + 15 * tid + 1;
        #pragma unroll
        for (int r = 0; r < RPC2; ++r)
            acc = fmaf(hs[r], base[(size_t)r * 4605], acc);
        g_part2[bx * 320 + tid] = acc;
    }
}

// ---------------- shared helpers ---------------------------------------------
__device__ __forceinline__ void fold_scalars(float* s_sh, const float* __restrict__ bd2,
                                             int sbase, int JB) {
    int tid = threadIdx.x;
    if (tid < JB) {
        int ks = sbase + tid;
        float v = bd2[15 * ks + 1];
        #pragma unroll
        for (int c = 0; c < KC2; ++c) v += g_part2[c * 320 + ks];
        s_sh[tid] = fmaxf(v, 0.f);
    }
}

// ---- seg1: 16 x 500 x 5121. warp-split-k, smem reduce, direct final write ---
// smem partition: s[0:16], h[16:16+8064] (504 rows x 16), red[8080:8080+4096]
__device__ __forceinline__ void seg1_body(
    float* smem, float* __restrict__ out, const float* __restrict__ bd2,
    const float* __restrict__ Wa, const float* __restrict__ ba,
    const float* __restrict__ Wb, const float* __restrict__ bb, int blk)
{
    const int O = 5121;
    float* s_sh = smem;
    float* h_sh = smem + 16;
    float* red  = smem + 8080;
    int tid = threadIdx.x;

    fold_scalars(s_sh, bd2, 0, 16);
    __syncthreads();

    // hidden: h[k][j] for k in [0,504), zero-padded beyond 500
    #pragma unroll
    for (int k = tid; k < 504; k += 256) {
        float av = 0.f, bv = 0.f;
        if (k < 500) { av = Wa[k]; bv = ba[k]; }
        float* hk = &h_sh[k * 16];
        #pragma unroll
        for (int j = 0; j < 16; ++j) {
            float v = (k < 500) ? fmaxf(fmaf(s_sh[j], av, bv), 0.f) : 0.f;
            hk[j] = v;
        }
    }
    __syncthreads();

    int w = tid >> 5, lane = tid & 31;
    int n = blk * 32 + lane;
    bool nok = (n < O);
    int k0 = w * 63;

    float acc[16];
    #pragma unroll
    for (int j = 0; j < 16; ++j) acc[j] = 0.f;

    #pragma unroll 21
    for (int r = 0; r < 63; ++r) {
        int k = k0 + r;
        float wv = (nok && k < 500) ? Wb[(size_t)k * O + n] : 0.f;
        const float* hr = &h_sh[k * 16];
        #pragma unroll
        for (int j = 0; j < 16; ++j)
            acc[j] = fmaf(hr[j], wv, acc[j]);
    }

    // reduce 8 warps in shared: red[w][j][lane]
    #pragma unroll
    for (int j = 0; j < 16; ++j)
        red[w * 512 + j * 32 + lane] = acc[j];
    __syncthreads();

    #pragma unroll
    for (int p = tid; p < 512; p += 256) {
        int j = p >> 5, ln = p & 31;
        int nn = blk * 32 + ln;
        if (nn < O) {
            float v = bb[nn];
            #pragma unroll
            for (int ww = 0; ww < 8; ++ww) v += red[ww * 512 + p];
            out[(size_t)j * O + nn] = fmaxf(v, 0.f);
        }
    }
}

// ---- direct segment: JB scalars x (256*CPT) cols, full K=100, final write ---
template<int JB, int CPT>
__device__ __forceinline__ void seg_direct(
    float* smem, float* __restrict__ out, const float* __restrict__ bd2,
    const float* __restrict__ Wa, const float* __restrict__ ba,
    const float* __restrict__ Wb, const float* __restrict__ bb,
    int O, int sbase, int jg0, int ct)
{
    float* s_sh = smem;
    float* h_sh = smem + 16;                   // [k][JB], 100*JB <= 400
    int tid = threadIdx.x;

    fold_scalars(s_sh, bd2, sbase + jg0, JB);
    __syncthreads();

    if (tid < 100) {
        float av = Wa[tid], bv = ba[tid];
        float* hk = &h_sh[tid * JB];
        #pragma unroll
        for (int j = 0; j < JB; ++j)
            hk[j] = fmaxf(fmaf(s_sh[j], av, bv), 0.f);
    }
    __syncthreads();

    int nb = ct * (256 * CPT) + tid;
    float acc[JB * CPT];
    #pragma unroll
    for (int i = 0; i < JB * CPT; ++i) acc[i] = 0.f;

    #pragma unroll 20
    for (int r = 0; r < 100; ++r) {
        const float* wrow = Wb + (size_t)r * O;
        float w[CPT];
        #pragma unroll
        for (int c = 0; c < CPT; ++c) {
            int n = nb + c * 256;
            w[c] = (n < O) ? wrow[n] : 0.f;
        }
        const float* hr = &h_sh[r * JB];
        #pragma unroll
        for (int j = 0; j < JB; ++j) {
            float hv = hr[j];
            #pragma unroll
            for (int c = 0; c < CPT; ++c)
                acc[j * CPT + c] = fmaf(hv, w[c], acc[j * CPT + c]);
        }
    }

    #pragma unroll
    for (int j = 0; j < JB; ++j) {
        #pragma unroll
        for (int c = 0; c < CPT; ++c) {
            int n = nb + c * 256;
            if (n < O)
                out[(size_t)(jg0 + j) * O + n] = fmaxf(acc[j * CPT + c] + bb[n], 0.f);
        }
    }
}

// seg1: 161 blocks (5121/32)   | seg3: 64 blocks (256 j / 4)
// seg2: 8 blocks (32 j / 4)    | seg4: 7 blocks (1542 cols / 256)
__global__ void __launch_bounds__(256) k_segments(
    float* __restrict__ out,
    const float* __restrict__ bd2,
    const float* __restrict__ W1a, const float* __restrict__ b1a, const float* __restrict__ W1b, const float* __restrict__ b1b,
    const float* __restrict__ W2a, const float* __restrict__ b2a, const float* __restrict__ W2b, const float* __restrict__ b2b,
    const float* __restrict__ W3a, const float* __restrict__ b3a, const float* __restrict__ W3b, const float* __restrict__ b3b,
    const float* __restrict__ W4a, const float* __restrict__ b4a, const float* __restrict__ W4b, const float* __restrict__ b4b)
{
    __shared__ float smem[12192];
    int b = blockIdx.x;
    if (b < 161) {
        seg1_body(smem, out, bd2, W1a, b1a, W1b, b1b, b);
    } else if (b < 225) {
        int jb = b - 161;
        seg_direct<4, 2>(smem, out + 90160, bd2, W3a, b3a, W3b, b3b, 321, 48, jb * 4, 0);
    } else if (b < 233) {
        int jb = b - 225;
        seg_direct<4, 2>(smem, out + 81936, bd2, W2a, b2a, W2b, b2b, 257, 16, jb * 4, 0);
    } else {
        int ct = b - 233;
        seg_direct<3, 1>(smem, out + 172336, bd2, W4a, b4a, W4b, b4b, 1542, 304, 0, ct);
    }
}

extern "C" void kernel_launch(void* const* d_in, const int* in_sizes, int n_in,
                              void* d_out, int out_size) {
    const float* x   = (const float*)d_in[0];
    const float* Wd1 = (const float*)d_in[1];
    const float* bd1 = (const float*)d_in[2];
    const float* Wd2 = (const float*)d_in[3];
    const float* bd2 = (const float*)d_in[4];
    const float* W1a = (const float*)d_in[5];
    const float* b1a = (const float*)d_in[6];
    const float* W1b = (const float*)d_in[7];
    const float* b1b = (const float*)d_in[8];
    const float* W2a = (const float*)d_in[9];
    const float* b2a = (const float*)d_in[10];
    const float* W2b = (const float*)d_in[11];
    const float* b2b = (const float*)d_in[12];
    const float* W3a = (const float*)d_in[13];
    const float* b3a = (const float*)d_in[14];
    const float* W3b = (const float*)d_in[15];
    const float* b3b = (const float*)d_in[16];
    const float* W4a = (const float*)d_in[17];
    const float* b4a = (const float*)d_in[18];
    const float* W4b = (const float*)d_in[19];
    const float* b4b = (const float*)d_in[20];
    float* out = (float*)d_out;

    k_l1_partial<<<NCH1, 256>>>(x, Wd1);
    k_mid<<<KC2, 512>>>(bd1, Wd2);
    k_segments<<<240, 256>>>(out, bd2,
                             W1a, b1a, W1b, b1b,
                             W2a, b2a, W2b, b2b,
                             W3a, b3a, W3b, b3b,
                             W4a, b4a, W4b, b4b);
}